// round 6
// baseline (speedup 1.0000x reference)
#include <cuda_runtime.h>
#include <cuda_bf16.h>
#include <math.h>

#define NN 100000
#define NE 1600000
#define NG 100
#define NH 8
#define NC 16
#define NF 128

// ---------------- scratch (static device globals) ---------------------------
__device__ __align__(16) __nv_bfloat16 g_hb[(size_t)NN * NF];  // 25.6 MB h (bf16)
__device__ __align__(16) float g_w[(size_t)NE * NH];           // 51.2 MB edge exp-weights
__device__ __align__(16) float g_asrc[NN * NH];
__device__ __align__(16) float g_adst[NN * NH];
__device__ __align__(16) float g_s[NN * NH];           // softmax denom, then inverted
__device__ __align__(16) float g_acc[NN * NC];         // head-averaged message accum
__device__ __align__(16) float g_colsum[NF];
__device__ __align__(16) float g_colsq[NF];
__device__ __align__(16) float g_scale[NF];
__device__ __align__(16) float g_shift[NF];
__device__ __align__(16) float g_pool[NG * NC];
__device__ __align__(16) float g_cnt[NG];

// vector reduction (no return) --------------------------------------------
__device__ __forceinline__ void red_v4(float* p, float a, float b, float c, float d) {
    asm volatile("red.global.add.v4.f32 [%0], {%1, %2, %3, %4};"
                 :: "l"(p), "f"(a), "f"(b), "f"(c), "f"(d) : "memory");
}

// packed f32x2 fma (sm_100+) ------------------------------------------------
__device__ __forceinline__ void fma_x2(unsigned long long& d,
                                       unsigned long long a, unsigned long long b) {
    asm("fma.rn.f32x2 %0, %1, %2, %0;" : "+l"(d) : "l"(a), "l"(b));
}

// ---------------- K0: zero accumulators ------------------------------------
__global__ void k_zero() {
    int i = blockIdx.x * blockDim.x + threadIdx.x;
    int st = gridDim.x * blockDim.x;
    for (int k = i; k < NN * NC; k += st) g_acc[k] = 0.f;
    if (i < NF) { g_colsum[i] = 0.f; g_colsq[i] = 0.f; }
    if (i < NG * NC) g_pool[i] = 0.f;
    if (i < NG) g_cnt[i] = 0.f;
}

// ---------------- K1: BN column stats --------------------------------------
__global__ void k_stats(const float* __restrict__ x) {
    __shared__ float ssum[NF];
    __shared__ float ssq[NF];
    int t = threadIdx.x;
    int lane = t & 31;
    int warp = t >> 5;
    int col = lane * 4;
    if (t < NF) { ssum[t] = 0.f; ssq[t] = 0.f; }
    __syncthreads();

    float s0 = 0.f, s1 = 0.f, s2 = 0.f, s3 = 0.f;
    float q0 = 0.f, q1 = 0.f, q2 = 0.f, q3 = 0.f;
    int row = blockIdx.x * 8 + warp;
    int step = gridDim.x * 8;
    for (int r = row; r < NN; r += step) {
        float4 v = *(const float4*)(x + (size_t)r * NF + col);
        s0 += v.x; s1 += v.y; s2 += v.z; s3 += v.w;
        q0 += v.x * v.x; q1 += v.y * v.y; q2 += v.z * v.z; q3 += v.w * v.w;
    }
    atomicAdd(&ssum[col + 0], s0); atomicAdd(&ssum[col + 1], s1);
    atomicAdd(&ssum[col + 2], s2); atomicAdd(&ssum[col + 3], s3);
    atomicAdd(&ssq[col + 0], q0);  atomicAdd(&ssq[col + 1], q1);
    atomicAdd(&ssq[col + 2], q2);  atomicAdd(&ssq[col + 3], q3);
    __syncthreads();
    if (t < NF) {
        atomicAdd(&g_colsum[t], ssum[t]);
        atomicAdd(&g_colsq[t], ssq[t]);
    }
}

// ---------------- K2: finalize BN scale/shift ------------------------------
__global__ void k_bnfin(const float* __restrict__ gamma, const float* __restrict__ beta) {
    int t = threadIdx.x;
    if (t < NF) {
        float mean = g_colsum[t] * (1.f / NN);
        float var = g_colsq[t] * (1.f / NN) - mean * mean;
        float sc = gamma[t] * rsqrtf(var + 1e-5f);
        g_scale[t] = sc;
        g_shift[t] = beta[t] - mean * sc;
    }
}

// ---------------- K3: fused BN + GEMM + attention logits --------------------
// 128 nodes/block, 256 threads, 8x8 microtile (as 8x4 f32x2 pairs), KCH=64.
#define KCH 64
#define SXT_STRIDE 132                           // 528 B/row = 33*16 (16B aligned)
#define SXT_FLOATS (KCH * SXT_STRIDE)
#define SW_FLOATS (KCH * 128)
#define GEMM_SMEM_BYTES ((SXT_FLOATS + SW_FLOATS) * 4)

__global__ void __launch_bounds__(256, 2)
k_gemm(const float* __restrict__ x, const float* __restrict__ W,
       const float* __restrict__ attS, const float* __restrict__ attD) {
    extern __shared__ float sm[];
    float* sxT = sm;                 // [k][row] stride 132
    float* sw = sm + SXT_FLOATS;     // [k][col]

    int t = threadIdx.x;
    int r0 = blockIdx.x * 128;
    int j = t & 15, i4 = t >> 4;

    unsigned long long accp[8][4];   // 8 rows x 4 f32x2 col-pairs
#pragma unroll
    for (int m = 0; m < 8; ++m)
#pragma unroll
        for (int n = 0; n < 4; ++n) accp[m][n] = 0ull;

    for (int k0 = 0; k0 < NF; k0 += KCH) {
        for (int i = t; i < SW_FLOATS / 4; i += 256)
            ((float4*)sw)[i] = ((const float4*)(W + (size_t)k0 * 128))[i];
        for (int i = t; i < 128 * KCH; i += 256) {
            int row = i >> 6, col = i & 63;
            int n = r0 + row;
            float v = 0.f;
            if (n < NN) v = x[(size_t)n * NF + k0 + col] * g_scale[k0 + col] + g_shift[k0 + col];
            sxT[col * SXT_STRIDE + row] = v;
        }
        __syncthreads();

        const float* aBase = sxT + i4 * 8;
        const float* bBase = sw + j * 8;
#pragma unroll 4
        for (int k = 0; k < KCH; ++k) {
            float4 a0 = *(const float4*)(aBase + k * SXT_STRIDE);
            float4 a1 = *(const float4*)(aBase + k * SXT_STRIDE + 4);
            float a[8] = {a0.x, a0.y, a0.z, a0.w, a1.x, a1.y, a1.z, a1.w};
            unsigned long long bv[4];
#pragma unroll
            for (int n = 0; n < 4; ++n) {
                double bd = *(const double*)(bBase + k * 128 + n * 2);  // LDS.64 pair
                bv[n] = __double_as_longlong(bd);
            }
#pragma unroll
            for (int m = 0; m < 8; ++m) {
                float2 ap = make_float2(a[m], a[m]);
                unsigned long long av = *(unsigned long long*)&ap;
#pragma unroll
                for (int n = 0; n < 4; ++n) fma_x2(accp[m][n], av, bv[n]);
            }
        }
        __syncthreads();
    }

    // unpack accumulators
    float acc[8][8];
#pragma unroll
    for (int m = 0; m < 8; ++m)
#pragma unroll
        for (int n = 0; n < 4; ++n) {
            float2 f = *(float2*)&accp[m][n];
            acc[m][2 * n] = f.x;
            acc[m][2 * n + 1] = f.y;
        }

    int rowsValid = NN - r0;
    if (rowsValid > 128) rowsValid = 128;

    // store h tile as bf16 straight from registers
#pragma unroll
    for (int m = 0; m < 8; ++m) {
        int row = i4 * 8 + m;
        if (row < rowsValid) {
            __nv_bfloat162 p[4];
#pragma unroll
            for (int c = 0; c < 4; ++c)
                p[c] = __float22bfloat162_rn(make_float2(acc[m][2 * c], acc[m][2 * c + 1]));
            *(uint4*)(g_hb + (size_t)(r0 + row) * NF + j * 8) = *(uint4*)p;
        }
    }

    // attention logits from fp32 regs: thread covers half of head hh=j>>1
    int hh = j >> 1;
    float asv[8], adv[8];
#pragma unroll
    for (int c = 0; c < 8; ++c) {
        asv[c] = attS[hh * 16 + (j & 1) * 8 + c];
        adv[c] = attD[hh * 16 + (j & 1) * 8 + c];
    }
#pragma unroll
    for (int m = 0; m < 8; ++m) {
        float ps = 0.f, pd = 0.f;
#pragma unroll
        for (int c = 0; c < 8; ++c) {
            ps = fmaf(acc[m][c], asv[c], ps);
            pd = fmaf(acc[m][c], adv[c], pd);
        }
        ps += __shfl_xor_sync(0xffffffffu, ps, 1);
        pd += __shfl_xor_sync(0xffffffffu, pd, 1);
        int row = i4 * 8 + m;
        if ((j & 1) == 0 && row < rowsValid) {
            int n = r0 + row;
            g_asrc[n * NH + hh] = ps;
            g_adst[n * NH + hh] = pd;
            float e = ps + pd;
            e = e > 0.f ? e : 0.2f * e;
            g_s[n * NH + hh] = __expf(e);   // self-loop contribution
        }
    }
}

// ---------------- K4: edge pass 1 — exp weights + denominators -------------
__device__ __forceinline__ float lrelu_exp(float a, float b) {
    float e = a + b;
    e = e > 0.f ? e : 0.2f * e;
    return __expf(e);
}

__global__ void k_edge_s(const int* __restrict__ ei) {
    int e = blockIdx.x * blockDim.x + threadIdx.x;
    if (e >= NE) return;
    int s = ei[e];
    int d = ei[NE + e];
    float4 a0 = *(const float4*)(g_asrc + s * NH);
    float4 a1 = *(const float4*)(g_asrc + s * NH + 4);
    float4 b0 = *(const float4*)(g_adst + d * NH);
    float4 b1 = *(const float4*)(g_adst + d * NH + 4);
    float4 w0 = make_float4(lrelu_exp(a0.x, b0.x), lrelu_exp(a0.y, b0.y),
                            lrelu_exp(a0.z, b0.z), lrelu_exp(a0.w, b0.w));
    float4 w1 = make_float4(lrelu_exp(a1.x, b1.x), lrelu_exp(a1.y, b1.y),
                            lrelu_exp(a1.z, b1.z), lrelu_exp(a1.w, b1.w));
    // store per-edge weights (coalesced)
    *(float4*)(g_w + (size_t)e * NH) = w0;
    *(float4*)(g_w + (size_t)e * NH + 4) = w1;
    float* sp = g_s + d * NH;
    red_v4(sp, w0.x, w0.y, w0.z, w0.w);
    red_v4(sp + 4, w1.x, w1.y, w1.z, w1.w);
}

// ---------------- K4b: invert denominators ---------------------------------
__global__ void k_sinv() {
    int i = blockIdx.x * blockDim.x + threadIdx.x;
    if (i < NN * NH) g_s[i] = __frcp_rn(g_s[i]);
}

// ---------------- K5: edge pass 2 — message scatter (1 thread/edge) --------
__global__ void k_edge_msg(const int* __restrict__ ei) {
    int e = blockIdx.x * blockDim.x + threadIdx.x;
    if (e >= NE) return;
    int s = ei[e];
    int d = ei[NE + e];
    float4 w0 = *(const float4*)(g_w + (size_t)e * NH);      // coalesced
    float4 w1 = *(const float4*)(g_w + (size_t)e * NH + 4);
    float4 s0 = *(const float4*)(g_s + d * NH);              // gather 32B
    float4 s1 = *(const float4*)(g_s + d * NH + 4);
    float al[8];
    al[0] = 0.125f * w0.x * s0.x;  al[1] = 0.125f * w0.y * s0.y;
    al[2] = 0.125f * w0.z * s0.z;  al[3] = 0.125f * w0.w * s0.w;
    al[4] = 0.125f * w1.x * s1.x;  al[5] = 0.125f * w1.y * s1.y;
    al[6] = 0.125f * w1.z * s1.z;  al[7] = 0.125f * w1.w * s1.w;

    const __nv_bfloat16* hrow = g_hb + (size_t)s * NF;
    float r[NC];
#pragma unroll
    for (int c = 0; c < NC; ++c) r[c] = 0.f;
#pragma unroll
    for (int h = 0; h < NH; ++h) {
        uint4 u0 = *(const uint4*)(hrow + h * 16);       // 8 bf16
        uint4 u1 = *(const uint4*)(hrow + h * 16 + 8);   // 8 bf16
        const __nv_bfloat162* p0 = (const __nv_bfloat162*)&u0;
        const __nv_bfloat162* p1 = (const __nv_bfloat162*)&u1;
        float ah = al[h];
#pragma unroll
        for (int q = 0; q < 4; ++q) {
            float2 f0 = __bfloat1622float2(p0[q]);
            float2 f1 = __bfloat1622float2(p1[q]);
            r[2 * q + 0] = fmaf(ah, f0.x, r[2 * q + 0]);
            r[2 * q + 1] = fmaf(ah, f0.y, r[2 * q + 1]);
            r[8 + 2 * q + 0] = fmaf(ah, f1.x, r[8 + 2 * q + 0]);
            r[8 + 2 * q + 1] = fmaf(ah, f1.y, r[8 + 2 * q + 1]);
        }
    }
    float* op = g_acc + (size_t)d * NC;
    red_v4(op + 0, r[0], r[1], r[2], r[3]);
    red_v4(op + 4, r[4], r[5], r[6], r[7]);
    red_v4(op + 8, r[8], r[9], r[10], r[11]);
    red_v4(op + 12, r[12], r[13], r[14], r[15]);
}

// ---------------- K6: node finalize (self-loop + bias + ELU + pool) --------
__global__ void k_node_final(const int* __restrict__ batch,
                             const float* __restrict__ bias) {
    int gt = blockIdx.x * blockDim.x + threadIdx.x;
    int n = gt >> 4, c = gt & 15;
    if (n >= NN) return;
    float v = g_acc[n * NC + c];
    const __nv_bfloat16* hr = g_hb + (size_t)n * NF;
#pragma unroll
    for (int h = 0; h < NH; ++h) {
        float a = g_asrc[n * NH + h] + g_adst[n * NH + h];
        a = a > 0.f ? a : 0.2f * a;
        float w = __expf(a) * g_s[n * NH + h];   // g_s holds 1/s
        v = fmaf(0.125f * w, __bfloat162float(hr[h * 16 + c]), v);
    }
    v += bias[c];
    v = v > 0.f ? v : expm1f(v);
    int b = batch[n];
    atomicAdd(&g_pool[b * NC + c], v);
    if (c == 0) atomicAdd(&g_cnt[b], 1.0f);
}

// ---------------- K7: pooled mean ------------------------------------------
__global__ void k_pool_div(float* __restrict__ out) {
    int i = blockIdx.x * blockDim.x + threadIdx.x;
    if (i < NG * NC) {
        int g = i >> 4;
        out[i] = g_pool[i] / fmaxf(g_cnt[g], 1.0f);
    }
}

// ---------------- launch ----------------------------------------------------
extern "C" void kernel_launch(void* const* d_in, const int* in_sizes, int n_in,
                              void* d_out, int out_size) {
    const float* x = (const float*)d_in[0];
    const int* ei = (const int*)d_in[1];
    const int* batch = (const int*)d_in[2];
    const float* gamma = (const float*)d_in[3];
    const float* beta = (const float*)d_in[4];
    const float* W = (const float*)d_in[5];
    const float* attS = (const float*)d_in[6];
    const float* attD = (const float*)d_in[7];
    const float* bias = (const float*)d_in[8];
    float* out = (float*)d_out;

    cudaFuncSetAttribute(k_gemm, cudaFuncAttributeMaxDynamicSharedMemorySize,
                         GEMM_SMEM_BYTES);

    k_zero<<<256, 256>>>();
    k_stats<<<512, 256>>>(x);
    k_bnfin<<<1, 128>>>(gamma, beta);
    k_gemm<<<(NN + 127) / 128, 256, GEMM_SMEM_BYTES>>>(x, W, attS, attD);
    k_edge_s<<<(NE + 255) / 256, 256>>>(ei);
    k_sinv<<<(NN * NH + 255) / 256, 256>>>();
    k_edge_msg<<<(NE + 255) / 256, 256>>>(ei);
    k_node_final<<<(NN * 16 + 255) / 256, 256>>>(batch, bias);
    k_pool_div<<<(NG * NC + 255) / 256, 256>>>(out);
}

// round 7
// speedup vs baseline: 1.7245x; 1.7245x over previous
#include <cuda_runtime.h>
#include <cuda_bf16.h>
#include <math.h>

#define NN 100000
#define NE 1600000
#define NG 100
#define NH 8
#define NC 16
#define NF 128

// ---------------- scratch (static device globals) ---------------------------
__device__ __align__(16) __nv_bfloat16 g_hb[(size_t)NN * NF];  // 25.6 MB h (bf16)
__device__ __align__(16) float g_asrc[NN * NH];
__device__ __align__(16) float g_adst[NN * NH];
__device__ __align__(16) float g_s[NN * NH];           // softmax denom, then inverted
__device__ __align__(16) float g_acc[NN * NC];         // head-averaged message accum
__device__ __align__(16) float g_colsum[NF];
__device__ __align__(16) float g_colsq[NF];
__device__ __align__(16) float g_scale[NF];
__device__ __align__(16) float g_shift[NF];
__device__ __align__(16) float g_pool[NG * NC];
__device__ __align__(16) float g_cnt[NG];

// vector reduction (no return) --------------------------------------------
__device__ __forceinline__ void red_v4(float* p, float a, float b, float c, float d) {
    asm volatile("red.global.add.v4.f32 [%0], {%1, %2, %3, %4};"
                 :: "l"(p), "f"(a), "f"(b), "f"(c), "f"(d) : "memory");
}

// ---------------- K0: zero accumulators ------------------------------------
__global__ void k_zero() {
    int i = blockIdx.x * blockDim.x + threadIdx.x;
    int st = gridDim.x * blockDim.x;
    for (int k = i; k < NN * NC; k += st) g_acc[k] = 0.f;
    if (i < NF) { g_colsum[i] = 0.f; g_colsq[i] = 0.f; }
    if (i < NG * NC) g_pool[i] = 0.f;
    if (i < NG) g_cnt[i] = 0.f;
}

// ---------------- K1: BN column stats --------------------------------------
__global__ void k_stats(const float* __restrict__ x) {
    __shared__ float ssum[NF];
    __shared__ float ssq[NF];
    int t = threadIdx.x;
    int lane = t & 31;
    int warp = t >> 5;
    int col = lane * 4;
    if (t < NF) { ssum[t] = 0.f; ssq[t] = 0.f; }
    __syncthreads();

    float s0 = 0.f, s1 = 0.f, s2 = 0.f, s3 = 0.f;
    float q0 = 0.f, q1 = 0.f, q2 = 0.f, q3 = 0.f;
    int row = blockIdx.x * 8 + warp;
    int step = gridDim.x * 8;
    for (int r = row; r < NN; r += step) {
        float4 v = *(const float4*)(x + (size_t)r * NF + col);
        s0 += v.x; s1 += v.y; s2 += v.z; s3 += v.w;
        q0 += v.x * v.x; q1 += v.y * v.y; q2 += v.z * v.z; q3 += v.w * v.w;
    }
    atomicAdd(&ssum[col + 0], s0); atomicAdd(&ssum[col + 1], s1);
    atomicAdd(&ssum[col + 2], s2); atomicAdd(&ssum[col + 3], s3);
    atomicAdd(&ssq[col + 0], q0);  atomicAdd(&ssq[col + 1], q1);
    atomicAdd(&ssq[col + 2], q2);  atomicAdd(&ssq[col + 3], q3);
    __syncthreads();
    if (t < NF) {
        atomicAdd(&g_colsum[t], ssum[t]);
        atomicAdd(&g_colsq[t], ssq[t]);
    }
}

// ---------------- K2: finalize BN scale/shift ------------------------------
__global__ void k_bnfin(const float* __restrict__ gamma, const float* __restrict__ beta) {
    int t = threadIdx.x;
    if (t < NF) {
        float mean = g_colsum[t] * (1.f / NN);
        float var = g_colsq[t] * (1.f / NN) - mean * mean;
        float sc = gamma[t] * rsqrtf(var + 1e-5f);
        g_scale[t] = sc;
        g_shift[t] = beta[t] - mean * sc;
    }
}

// ---------------- K3: fused BN + GEMM + attention logits --------------------
// 128 nodes/block, 256 threads, 8x8 microtile, KCH=64 (2 CTAs/SM). (R5 version)
#define KCH 64
#define SXT_STRIDE 132                           // 528 B/row = 33*16 (16B aligned)
#define SXT_FLOATS (KCH * SXT_STRIDE)
#define SW_FLOATS (KCH * 128)
#define GEMM_SMEM_BYTES ((SXT_FLOATS + SW_FLOATS) * 4)

__global__ void __launch_bounds__(256, 2)
k_gemm(const float* __restrict__ x, const float* __restrict__ W,
       const float* __restrict__ attS, const float* __restrict__ attD) {
    extern __shared__ float sm[];
    float* sxT = sm;                 // [k][row] stride 132
    float* sw = sm + SXT_FLOATS;     // [k][col]

    int t = threadIdx.x;
    int r0 = blockIdx.x * 128;
    int j = t & 15, i4 = t >> 4;

    float acc[8][8];
#pragma unroll
    for (int m = 0; m < 8; ++m)
#pragma unroll
        for (int n = 0; n < 8; ++n) acc[m][n] = 0.f;

    for (int k0 = 0; k0 < NF; k0 += KCH) {
        for (int i = t; i < SW_FLOATS / 4; i += 256)
            ((float4*)sw)[i] = ((const float4*)(W + (size_t)k0 * 128))[i];
        for (int i = t; i < 128 * KCH; i += 256) {
            int row = i >> 6, col = i & 63;
            int n = r0 + row;
            float v = 0.f;
            if (n < NN) v = x[(size_t)n * NF + k0 + col] * g_scale[k0 + col] + g_shift[k0 + col];
            sxT[col * SXT_STRIDE + row] = v;
        }
        __syncthreads();

        const float* aBase = sxT + i4 * 8;
        const float* bBase = sw + j * 8;
#pragma unroll 4
        for (int k = 0; k < KCH; ++k) {
            float4 a0 = *(const float4*)(aBase + k * SXT_STRIDE);
            float4 a1 = *(const float4*)(aBase + k * SXT_STRIDE + 4);
            float4 b0 = *(const float4*)(bBase + k * 128);
            float4 b1 = *(const float4*)(bBase + k * 128 + 4);
            float a[8] = {a0.x, a0.y, a0.z, a0.w, a1.x, a1.y, a1.z, a1.w};
            float b[8] = {b0.x, b0.y, b0.z, b0.w, b1.x, b1.y, b1.z, b1.w};
#pragma unroll
            for (int m = 0; m < 8; ++m)
#pragma unroll
                for (int n = 0; n < 8; ++n) acc[m][n] = fmaf(a[m], b[n], acc[m][n]);
        }
        __syncthreads();
    }

    int rowsValid = NN - r0;
    if (rowsValid > 128) rowsValid = 128;

    // store h tile as bf16 straight from registers
#pragma unroll
    for (int m = 0; m < 8; ++m) {
        int row = i4 * 8 + m;
        if (row < rowsValid) {
            __nv_bfloat162 p[4];
#pragma unroll
            for (int c = 0; c < 4; ++c)
                p[c] = __float22bfloat162_rn(make_float2(acc[m][2 * c], acc[m][2 * c + 1]));
            *(uint4*)(g_hb + (size_t)(r0 + row) * NF + j * 8) = *(uint4*)p;
        }
    }

    // attention logits from fp32 regs: thread covers half of head hh=j>>1
    int hh = j >> 1;
    float asv[8], adv[8];
#pragma unroll
    for (int c = 0; c < 8; ++c) {
        asv[c] = attS[hh * 16 + (j & 1) * 8 + c];
        adv[c] = attD[hh * 16 + (j & 1) * 8 + c];
    }
#pragma unroll
    for (int m = 0; m < 8; ++m) {
        float ps = 0.f, pd = 0.f;
#pragma unroll
        for (int c = 0; c < 8; ++c) {
            ps = fmaf(acc[m][c], asv[c], ps);
            pd = fmaf(acc[m][c], adv[c], pd);
        }
        ps += __shfl_xor_sync(0xffffffffu, ps, 1);
        pd += __shfl_xor_sync(0xffffffffu, pd, 1);
        int row = i4 * 8 + m;
        if ((j & 1) == 0 && row < rowsValid) {
            int n = r0 + row;
            g_asrc[n * NH + hh] = ps;
            g_adst[n * NH + hh] = pd;
            float e = ps + pd;
            e = e > 0.f ? e : 0.2f * e;
            g_s[n * NH + hh] = __expf(e);   // self-loop contribution
        }
    }
}

// ---------------- K4: edge pass 1 — softmax denominators -------------------
__device__ __forceinline__ float lrelu_exp(float a, float b) {
    float e = a + b;
    e = e > 0.f ? e : 0.2f * e;
    return __expf(e);
}

__global__ void k_edge_s(const int* __restrict__ ei) {
    int e = blockIdx.x * blockDim.x + threadIdx.x;
    if (e >= NE) return;
    int s = ei[e];
    int d = ei[NE + e];
    float4 a0 = *(const float4*)(g_asrc + s * NH);
    float4 a1 = *(const float4*)(g_asrc + s * NH + 4);
    float4 b0 = *(const float4*)(g_adst + d * NH);
    float4 b1 = *(const float4*)(g_adst + d * NH + 4);
    float* sp = g_s + d * NH;
    red_v4(sp, lrelu_exp(a0.x, b0.x), lrelu_exp(a0.y, b0.y),
               lrelu_exp(a0.z, b0.z), lrelu_exp(a0.w, b0.w));
    red_v4(sp + 4, lrelu_exp(a1.x, b1.x), lrelu_exp(a1.y, b1.y),
                   lrelu_exp(a1.z, b1.z), lrelu_exp(a1.w, b1.w));
}

// ---------------- K4b: invert denominators ---------------------------------
__global__ void k_sinv() {
    int i = blockIdx.x * blockDim.x + threadIdx.x;
    if (i < NN * NH) g_s[i] = __frcp_rn(g_s[i]);
}

// ---------------- K5: edge pass 2 — message scatter (4 threads/edge) -------
// Thread q computes alpha only for head-pair q (2 exps, 24B of gathers), the
// 4 threads swap pairs via shfl_xor, then each fmas its 4 output channels.
__global__ void k_edge_msg(const int* __restrict__ ei) {
    int gt = blockIdx.x * blockDim.x + threadIdx.x;
    int e = gt >> 2, q = gt & 3;
    if (e >= NE) return;
    int s = ei[e];
    int d = ei[NE + e];

    // per-thread 8B slices of the attention arrays (head pair q)
    float2 as2 = *(const float2*)(g_asrc + s * NH + q * 2);
    float2 ad2 = *(const float2*)(g_adst + d * NH + q * 2);
    float2 si2 = *(const float2*)(g_s + d * NH + q * 2);
    float2 alq;
    alq.x = 0.125f * lrelu_exp(as2.x, ad2.x) * si2.x;
    alq.y = 0.125f * lrelu_exp(as2.y, ad2.y) * si2.y;

    // exchange pairs: after shuffles, thread holds pairs of indices q^1,q^2,q^3
    unsigned long long v0 = *(unsigned long long*)&alq;
    unsigned long long v1 = __shfl_xor_sync(0xffffffffu, v0, 1);
    unsigned long long v2 = __shfl_xor_sync(0xffffffffu, v0, 2);
    unsigned long long v3 = __shfl_xor_sync(0xffffffffu, v1, 2);  // pair q^3
    float2 p1 = *(float2*)&v1, p2 = *(float2*)&v2, p3 = *(float2*)&v3;

    float al[8];
#pragma unroll
    for (int i = 0; i < 4; ++i) {
        int r = i ^ q;
        float2 p = (r == 0) ? alq : (r == 1) ? p1 : (r == 2) ? p2 : p3;
        al[2 * i] = p.x;
        al[2 * i + 1] = p.y;
    }

    const __nv_bfloat16* hrow = g_hb + (size_t)s * NF + q * 4;
    float r0 = 0.f, r1 = 0.f, r2 = 0.f, r3 = 0.f;
#pragma unroll
    for (int h = 0; h < NH; ++h) {
        __nv_bfloat162 p01 = *(const __nv_bfloat162*)(hrow + h * 16);
        __nv_bfloat162 p23 = *(const __nv_bfloat162*)(hrow + h * 16 + 2);
        float2 f01 = __bfloat1622float2(p01);
        float2 f23 = __bfloat1622float2(p23);
        r0 = fmaf(al[h], f01.x, r0);
        r1 = fmaf(al[h], f01.y, r1);
        r2 = fmaf(al[h], f23.x, r2);
        r3 = fmaf(al[h], f23.y, r3);
    }
    red_v4(g_acc + d * NC + q * 4, r0, r1, r2, r3);
}

// ---------------- K6: node finalize (self-loop + bias + ELU + pool) --------
__global__ void k_node_final(const int* __restrict__ batch,
                             const float* __restrict__ bias) {
    int gt = blockIdx.x * blockDim.x + threadIdx.x;
    int n = gt >> 4, c = gt & 15;
    if (n >= NN) return;
    float v = g_acc[n * NC + c];
    const __nv_bfloat16* hr = g_hb + (size_t)n * NF;
#pragma unroll
    for (int h = 0; h < NH; ++h) {
        float a = g_asrc[n * NH + h] + g_adst[n * NH + h];
        a = a > 0.f ? a : 0.2f * a;
        float w = __expf(a) * g_s[n * NH + h];   // g_s holds 1/s
        v = fmaf(0.125f * w, __bfloat162float(hr[h * 16 + c]), v);
    }
    v += bias[c];
    v = v > 0.f ? v : expm1f(v);
    int b = batch[n];
    atomicAdd(&g_pool[b * NC + c], v);
    if (c == 0) atomicAdd(&g_cnt[b], 1.0f);
}

// ---------------- K7: pooled mean ------------------------------------------
__global__ void k_pool_div(float* __restrict__ out) {
    int i = blockIdx.x * blockDim.x + threadIdx.x;
    if (i < NG * NC) {
        int g = i >> 4;
        out[i] = g_pool[i] / fmaxf(g_cnt[g], 1.0f);
    }
}

// ---------------- launch ----------------------------------------------------
extern "C" void kernel_launch(void* const* d_in, const int* in_sizes, int n_in,
                              void* d_out, int out_size) {
    const float* x = (const float*)d_in[0];
    const int* ei = (const int*)d_in[1];
    const int* batch = (const int*)d_in[2];
    const float* gamma = (const float*)d_in[3];
    const float* beta = (const float*)d_in[4];
    const float* W = (const float*)d_in[5];
    const float* attS = (const float*)d_in[6];
    const float* attD = (const float*)d_in[7];
    const float* bias = (const float*)d_in[8];
    float* out = (float*)d_out;

    cudaFuncSetAttribute(k_gemm, cudaFuncAttributeMaxDynamicSharedMemorySize,
                         GEMM_SMEM_BYTES);

    k_zero<<<256, 256>>>();
    k_stats<<<512, 256>>>(x);
    k_bnfin<<<1, 128>>>(gamma, beta);
    k_gemm<<<(NN + 127) / 128, 256, GEMM_SMEM_BYTES>>>(x, W, attS, attD);
    k_edge_s<<<(NE + 255) / 256, 256>>>(ei);
    k_sinv<<<(NN * NH + 255) / 256, 256>>>();
    k_edge_msg<<<(NE * 4 + 255) / 256, 256>>>(ei);
    k_node_final<<<(NN * 16 + 255) / 256, 256>>>(batch, bias);
    k_pool_div<<<(NG * NC + 255) / 256, 256>>>(out);
}